// round 8
// baseline (speedup 1.0000x reference)
#include <cuda_runtime.h>
#include <cuda_fp16.h>
#include <cstdint>
#include <math.h>

#define NB 64
#define NT 256
#define ND 512

// fp16 scratch: transposed + sqrt(w)-scaled + RN-rounded, layout [b][d][t]
__device__ __half g_rh[(size_t)NB * ND * NT];
__device__ __half g_ih[(size_t)NB * ND * NT];

// ---------- helpers ----------
__device__ __forceinline__ uint32_t s2u(const void* p) {
    uint32_t a;
    asm("{ .reg .u64 t; cvta.to.shared.u64 t, %1; cvt.u32.u64 %0, t; }" : "=r"(a) : "l"(p));
    return a;
}
__device__ __forceinline__ void cpa16(uint32_t dst, const void* src) {
    asm volatile("cp.async.cg.shared.global [%0], [%1], 16;" :: "r"(dst), "l"(src));
}
__device__ __forceinline__ void ldsm4(uint32_t r[4], uint32_t addr) {
    asm volatile("ldmatrix.sync.aligned.m8n8.x4.shared.b16 {%0,%1,%2,%3}, [%4];"
                 : "=r"(r[0]), "=r"(r[1]), "=r"(r[2]), "=r"(r[3]) : "r"(addr));
}
__device__ __forceinline__ void mma16816(float c[4], const uint32_t a[4],
                                         uint32_t b0, uint32_t b1) {
    asm volatile(
        "mma.sync.aligned.m16n8k16.row.col.f32.f16.f16.f32 "
        "{%0,%1,%2,%3}, {%4,%5,%6,%7}, {%8,%9}, {%0,%1,%2,%3};"
        : "+f"(c[0]), "+f"(c[1]), "+f"(c[2]), "+f"(c[3])
        : "r"(a[0]), "r"(a[1]), "r"(a[2]), "r"(a[3]), "r"(b0), "r"(b1));
}

// ---------- Pass 1: transpose + sqrt(w) scale + fp16 round ----------
__global__ void __launch_bounds__(256) prep_kernel(
    const float* __restrict__ real, const float* __restrict__ imag,
    const float* __restrict__ weight) {
    __shared__ float tr[32][33];
    __shared__ float ti[32][33];
    __shared__ float sw[32];
    int b = blockIdx.z;
    int d0 = blockIdx.x * 32, t0 = blockIdx.y * 32;
    int tid = threadIdx.x;
    int lx = tid & 31, ly = tid >> 5;  // ly 0..7
    if (tid < 32) sw[tid] = sqrtf(weight[b * NT + t0 + tid]);
    const float* rb = real + ((size_t)b * NT + t0) * ND + d0;
    const float* ib = imag + ((size_t)b * NT + t0) * ND + d0;
#pragma unroll
    for (int p = 0; p < 4; p++) {
        int t = p * 8 + ly;
        tr[t][lx] = rb[(size_t)t * ND + lx];
        ti[t][lx] = ib[(size_t)t * ND + lx];
    }
    __syncthreads();
    __half* orp = g_rh + ((size_t)b * ND + d0) * NT + t0;
    __half* oip = g_ih + ((size_t)b * ND + d0) * NT + t0;
    float s = sw[lx];
#pragma unroll
    for (int p = 0; p < 4; p++) {
        int d = p * 8 + ly;
        orp[(size_t)d * NT + lx] = __float2half_rn(tr[lx][d] * s);
        oip[(size_t)d * NT + lx] = __float2half_rn(ti[lx][d] * s);
    }
}

// ---------- Pass 2: fp16 mma.sync batched GEMM ----------
// Tiles: 128 rows x 32 k halves, row stride 80 B (conflict-free permutation).
#define ROW_B 80
#define TILE_B (128 * ROW_B)      // 10240
#define STAGE_B (4 * TILE_B)      // 40960
#define SMEM_REQ (2 * STAGE_B)    // 81920

__global__ void __launch_bounds__(256, 1) gemm_kernel(float* __restrict__ out) {
    extern __shared__ char smem[];
    uint32_t sb = s2u(smem);
    int tid = threadIdx.x, lane = tid & 31, wid = tid >> 5;
    int wm = wid & 3, wn = wid >> 2;  // 4 warps along M(128), 2 along N(128)
    int b = blockIdx.z, di = blockIdx.y, ei = blockIdx.x;

    // tile order: 0=rh(d-block) 1=ih(d) 2=rh(e-block) 3=ih(e)
    const __half* srcs[4];
    srcs[0] = g_rh + ((size_t)b * ND + di * 128) * NT;
    srcs[1] = g_ih + ((size_t)b * ND + di * 128) * NT;
    srcs[2] = g_rh + ((size_t)b * ND + ei * 128) * NT;
    srcs[3] = g_ih + ((size_t)b * ND + ei * 128) * NT;

    int jr = tid & 3, rr = tid >> 2;  // 16B chunk in row / base row (0..63)

    auto issue = [&](int c, int s) {
#pragma unroll
        for (int m = 0; m < 4; m++) {
            uint32_t tb = sb + (uint32_t)s * STAGE_B + (uint32_t)m * TILE_B;
#pragma unroll
            for (int rep = 0; rep < 2; rep++) {
                int row = rep * 64 + rr;
                cpa16(tb + (uint32_t)(row * ROW_B + jr * 16),
                      srcs[m] + (size_t)row * NT + c * 32 + jr * 8);
            }
        }
        asm volatile("cp.async.commit_group;" ::: "memory");
    };

    float accS[2][8][4], accD[2][8][4];
#pragma unroll
    for (int mt = 0; mt < 2; mt++)
#pragma unroll
        for (int nt = 0; nt < 8; nt++)
#pragma unroll
            for (int q = 0; q < 4; q++) { accS[mt][nt][q] = 0.f; accD[mt][nt][q] = 0.f; }

    issue(0, 0);
    for (int c = 0; c < 8; c++) {
        int s = c & 1;
        if (c < 7) {
            issue(c + 1, s ^ 1);
            asm volatile("cp.async.wait_group 1;" ::: "memory");
        } else {
            asm volatile("cp.async.wait_group 0;" ::: "memory");
        }
        __syncthreads();
        uint32_t stb = sb + (uint32_t)s * STAGE_B;
#pragma unroll
        for (int kk = 0; kk < 2; kk++) {
            int colb = kk * 32 + (lane >> 4) * 16;  // byte col for this lane's matrix
            // A fragments (rows = d-block)
            uint32_t rA[2][4], iA[2][4];
#pragma unroll
            for (int mt = 0; mt < 2; mt++) {
                int row = wm * 32 + mt * 16 + (lane & 15);
                ldsm4(rA[mt], stb + 0 * TILE_B + row * ROW_B + colb);
                ldsm4(iA[mt], stb + 1 * TILE_B + row * ROW_B + colb);
            }
            // B fragments (rows = e-block); x4 covers 2 n-tiles:
            // regs {q0,q1,q2,q3}: nt_even={q0,q2}, nt_odd={q1,q3}
            uint32_t rB[4][4], iB[4][4];
#pragma unroll
            for (int p = 0; p < 4; p++) {
                int row = wn * 64 + p * 16 + (lane & 15);
                ldsm4(rB[p], stb + 2 * TILE_B + row * ROW_B + colb);
                ldsm4(iB[p], stb + 3 * TILE_B + row * ROW_B + colb);
            }
            // S += r.r + i.i
#pragma unroll
            for (int mt = 0; mt < 2; mt++)
#pragma unroll
                for (int p = 0; p < 4; p++) {
                    mma16816(accS[mt][2 * p + 0], rA[mt], rB[p][0], rB[p][2]);
                    mma16816(accS[mt][2 * p + 1], rA[mt], rB[p][1], rB[p][3]);
                    mma16816(accS[mt][2 * p + 0], iA[mt], iB[p][0], iB[p][2]);
                    mma16816(accS[mt][2 * p + 1], iA[mt], iB[p][1], iB[p][3]);
                }
            // negate rA in place (fp16x2 sign flip)
#pragma unroll
            for (int mt = 0; mt < 2; mt++)
#pragma unroll
                for (int q = 0; q < 4; q++) rA[mt][q] ^= 0x80008000u;
            // D += i.r + (-r).i
#pragma unroll
            for (int mt = 0; mt < 2; mt++)
#pragma unroll
                for (int p = 0; p < 4; p++) {
                    mma16816(accD[mt][2 * p + 0], iA[mt], rB[p][0], rB[p][2]);
                    mma16816(accD[mt][2 * p + 1], iA[mt], rB[p][1], rB[p][3]);
                    mma16816(accD[mt][2 * p + 0], rA[mt], iB[p][0], iB[p][2]);
                    mma16816(accD[mt][2 * p + 1], rA[mt], iB[p][1], iB[p][3]);
                }
        }
        __syncthreads();  // all warps done reading stage s before it is refilled
    }

    // Epilogue: C frag: c0,c1 = row g cols 2t,2t+1 ; c2,c3 = row g+8
    size_t ob = (size_t)NB * ND * ND;
#pragma unroll
    for (int mt = 0; mt < 2; mt++) {
        int gd = di * 128 + wm * 32 + mt * 16 + (lane >> 2);
#pragma unroll
        for (int nt = 0; nt < 8; nt++) {
            int ge = ei * 128 + wn * 64 + nt * 8 + (lane & 3) * 2;
            float* pr = out + ((size_t)b * ND + gd) * ND + ge;
            *reinterpret_cast<float2*>(pr) =
                make_float2(accS[mt][nt][0], accS[mt][nt][1]);
            *reinterpret_cast<float2*>(pr + 8 * ND) =
                make_float2(accS[mt][nt][2], accS[mt][nt][3]);
            float* pi = pr + ob;
            *reinterpret_cast<float2*>(pi) =
                make_float2(accD[mt][nt][0], accD[mt][nt][1]);
            *reinterpret_cast<float2*>(pi + 8 * ND) =
                make_float2(accD[mt][nt][2], accD[mt][nt][3]);
        }
    }
}

extern "C" void kernel_launch(void* const* d_in, const int* in_sizes, int n_in,
                              void* d_out, int out_size) {
    const float* real = (const float*)d_in[0];
    const float* imag = (const float*)d_in[1];
    const float* weight = (const float*)d_in[2];
    float* out = (float*)d_out;

    cudaFuncSetAttribute(gemm_kernel, cudaFuncAttributeMaxDynamicSharedMemorySize, SMEM_REQ);

    dim3 g1(ND / 32, NT / 32, NB);  // (16, 8, 64)
    prep_kernel<<<g1, 256>>>(real, imag, weight);

    dim3 g2(4, 4, NB);  // (ei, di, b) = 1024 CTAs
    gemm_kernel<<<g2, 256, SMEM_REQ>>>(out);
}